// round 1
// baseline (speedup 1.0000x reference)
#include <cuda_runtime.h>
#include <cuda_bf16.h>
#include <cstdint>

// Problem shapes (fixed by the dataset)
#define BB   8
#define SS   256
#define HH   768
#define KK   256
#define PP   50

// 2*log2(e): stage-1 pre-scales so fused kernel computes tanh(x) = 1 - 2/(ex2(s)+1)
// with s = Lrow[k] + Rrow[k] = 2*log2(e)*(left+right+bias)  -> ex2(s) = exp(2x).
#define TANH_PRESCALE 2.8853900817779268f

// Scratch (device globals: no allocation allowed in kernel_launch)
__device__ float g_L[BB * SS * KK];   // 2M floats
__device__ float g_R[BB * SS * KK];   // 2M floats

// ---------------------------------------------------------------------------
// Stage 1: L = (X @ U) * c   ;   R = (X @ W + b_s) * c
// X: (2048, 768), U/W: (768, 256). Classic 64x64 tile, 16x16 threads, 4x4 micro.
// blockIdx.z selects U->g_L (z=0) or W->g_R (z=1, adds bias).
// ---------------------------------------------------------------------------
__global__ __launch_bounds__(256) void proj_kernel(
    const float* __restrict__ X,
    const float* __restrict__ U,
    const float* __restrict__ W,
    const float* __restrict__ bs)
{
    const int z  = blockIdx.z;
    const float* Bm = z ? W : U;
    float* out      = z ? g_R : g_L;

    __shared__ float As[64][17];   // padded: conflict-free column reads
    __shared__ float Bs[16][64];

    const int tx  = threadIdx.x;       // 0..15
    const int ty  = threadIdx.y;       // 0..15
    const int tid = ty * 16 + tx;
    const int m0  = blockIdx.y * 64;
    const int n0  = blockIdx.x * 64;

    float acc[4][4];
#pragma unroll
    for (int u = 0; u < 4; u++)
#pragma unroll
        for (int v = 0; v < 4; v++) acc[u][v] = 0.0f;

    for (int k0 = 0; k0 < HH; k0 += 16) {
        // load X tile 64x16
#pragma unroll
        for (int l = 0; l < 4; l++) {
            int idx = tid + l * 256;
            int r = idx >> 4, c = idx & 15;
            As[r][c] = X[(size_t)(m0 + r) * HH + k0 + c];
        }
        // load B tile 16x64
#pragma unroll
        for (int l = 0; l < 4; l++) {
            int idx = tid + l * 256;
            int r = idx >> 6, c = idx & 63;
            Bs[r][c] = Bm[(size_t)(k0 + r) * KK + n0 + c];
        }
        __syncthreads();

#pragma unroll
        for (int kk = 0; kk < 16; kk++) {
            float a[4], b[4];
#pragma unroll
            for (int u = 0; u < 4; u++) a[u] = As[ty * 4 + u][kk];
#pragma unroll
            for (int v = 0; v < 4; v++) b[v] = Bs[kk][tx * 4 + v];
#pragma unroll
            for (int u = 0; u < 4; u++)
#pragma unroll
                for (int v = 0; v < 4; v++)
                    acc[u][v] = fmaf(a[u], b[v], acc[u][v]);
        }
        __syncthreads();
    }

#pragma unroll
    for (int u = 0; u < 4; u++) {
        int row = m0 + ty * 4 + u;
#pragma unroll
        for (int v = 0; v < 4; v++) {
            int col = n0 + tx * 4 + v;
            float val = acc[u][v];
            if (z) val += bs[col];
            out[(size_t)row * KK + col] = val * TANH_PRESCALE;
        }
    }
}

// ---------------------------------------------------------------------------
// Stage 2: out[b,i,j,p] = sum_k tanh(left[b,i,k]+right[b,j,k]+b_s[k]) * v[k,p]
// CTA = (b, 16 i-rows, 64 j-rows) -> 1024 output rows, 4 passes of 256 threads.
// Each thread owns one (i,j) row: 50 fp32 accumulators, k-loop over 256.
// tanh via exact identity with ex2.approx + rcp.approx (MUFU), hidden by FMA.
// ---------------------------------------------------------------------------
#define RSTRIDE 257                     // conflict-free: bank = (j + k) % 32
#define VSTRIDE 52                      // 208B rows: float4-aligned
#define SM_RIGHT_ELEMS (64 * RSTRIDE)   // 16448
#define SM_LEFT_ELEMS  (16 * RSTRIDE)   // 4112
#define SM_V_ELEMS     (KK * VSTRIDE)   // 13312
#define SMEM2_BYTES ((SM_RIGHT_ELEMS + SM_LEFT_ELEMS + SM_V_ELEMS) * 4)  // 135488

__global__ __launch_bounds__(256) void fused_kernel(
    const float* __restrict__ v,
    float* __restrict__ out)
{
    extern __shared__ float sm[];
    float* s_right = sm;
    float* s_left  = sm + SM_RIGHT_ELEMS;
    float* s_v     = sm + SM_RIGHT_ELEMS + SM_LEFT_ELEMS;

    const int tid = threadIdx.x;
    const int b   = blockIdx.z;
    const int i0  = blockIdx.y * 16;
    const int j0  = blockIdx.x * 64;

    // ---- fill shared memory ----
    // right tile: 64 rows x 256
    for (int idx = tid; idx < 64 * KK; idx += 256) {
        int r = idx >> 8, c = idx & 255;
        s_right[r * RSTRIDE + c] = g_R[((size_t)(b * SS + j0 + r)) * KK + c];
    }
    // left tile: 16 rows x 256
    for (int idx = tid; idx < 16 * KK; idx += 256) {
        int r = idx >> 8, c = idx & 255;
        s_left[r * RSTRIDE + c] = g_L[((size_t)(b * SS + i0 + r)) * KK + c];
    }
    // v: 256 x 50, padded to 52/row
    for (int idx = tid; idx < SM_V_ELEMS; idx += 256) {
        int r = idx / VSTRIDE;
        int c = idx - r * VSTRIDE;
        s_v[idx] = (c < PP) ? v[r * PP + c] : 0.0f;
    }
    __syncthreads();

#pragma unroll 1
    for (int pass = 0; pass < 4; pass++) {
        const int m  = pass * 256 + tid;
        const int il = m >> 6;
        const int jl = m & 63;
        const float* Lr = s_left  + il * RSTRIDE;
        const float* Rr = s_right + jl * RSTRIDE;

        float acc[PP];
#pragma unroll
        for (int p = 0; p < PP; p++) acc[p] = 0.0f;

#pragma unroll 1
        for (int k0 = 0; k0 < KK; k0 += 8) {
            float tv[8];
#pragma unroll
            for (int u = 0; u < 8; u++) {
                float s = Lr[k0 + u] + Rr[k0 + u];      // = 2*log2e*(l+r+b)
                float e, q;
                asm("ex2.approx.f32 %0, %1;" : "=f"(e) : "f"(s));   // exp(2x)
                float d = e + 1.0f;
                asm("rcp.approx.f32 %0, %1;" : "=f"(q) : "f"(d));
                tv[u] = fmaf(-2.0f, q, 1.0f);           // tanh(x) = 1 - 2/(e+1)
            }
#pragma unroll
            for (int u = 0; u < 8; u++) {
                const float* vr = s_v + (k0 + u) * VSTRIDE;
                const float t = tv[u];
#pragma unroll
                for (int p4 = 0; p4 < 12; p4++) {
                    float4 vv = *reinterpret_cast<const float4*>(vr + p4 * 4);
                    acc[p4 * 4 + 0] = fmaf(t, vv.x, acc[p4 * 4 + 0]);
                    acc[p4 * 4 + 1] = fmaf(t, vv.y, acc[p4 * 4 + 1]);
                    acc[p4 * 4 + 2] = fmaf(t, vv.z, acc[p4 * 4 + 2]);
                    acc[p4 * 4 + 3] = fmaf(t, vv.w, acc[p4 * 4 + 3]);
                }
                float2 v2 = *reinterpret_cast<const float2*>(vr + 48);
                acc[48] = fmaf(t, v2.x, acc[48]);
                acc[49] = fmaf(t, v2.y, acc[49]);
            }
        }

        float* op = out + ((size_t)((b * SS + i0 + il) * SS + (j0 + jl))) * PP;
#pragma unroll
        for (int p2 = 0; p2 < 25; p2++) {
            float2 w;
            w.x = acc[2 * p2];
            w.y = acc[2 * p2 + 1];
            *reinterpret_cast<float2*>(op + 2 * p2) = w;
        }
    }
}

// ---------------------------------------------------------------------------
extern "C" void kernel_launch(void* const* d_in, const int* in_sizes, int n_in,
                              void* d_out, int out_size)
{
    (void)in_sizes; (void)n_in; (void)out_size;
    const float* x   = (const float*)d_in[0];
    const float* u_a = (const float*)d_in[1];
    const float* w_a = (const float*)d_in[2];
    const float* b_s = (const float*)d_in[3];
    const float* v   = (const float*)d_in[4];
    float* out       = (float*)d_out;

    // Stage 1: projections (z=0 -> g_L, z=1 -> g_R)
    {
        dim3 grid(KK / 64, (BB * SS) / 64, 2);   // (4, 32, 2)
        dim3 block(16, 16);
        proj_kernel<<<grid, block>>>(x, u_a, w_a, b_s);
    }

    // Stage 2: fused tanh + contraction
    {
        static int smem_set = -1;
        cudaFuncSetAttribute(fused_kernel,
                             cudaFuncAttributeMaxDynamicSharedMemorySize,
                             SMEM2_BYTES);
        (void)smem_set;
        dim3 grid(SS / 64, SS / 16, BB);         // (4, 16, 8)
        fused_kernel<<<grid, 256, SMEM2_BYTES>>>(v, out);
    }
}

// round 4
// speedup vs baseline: 2.0822x; 2.0822x over previous
#include <cuda_runtime.h>
#include <cuda_bf16.h>
#include <cstdint>

// Shapes (fixed)
#define BB   8
#define SS   256
#define HH   768
#define KK   256
#define PP   50

// 2*log2(e): tanh(x) = 1 - 2/(exp2(c*a)*exp2(c*b) + 1),  a+b = x
#define TANH_PRESCALE 2.8853900817779268f

// Device scratch (no allocation allowed in kernel_launch)
__device__ float g_EL[BB * SS * KK];   // exp2(c * left)
__device__ float g_ER[BB * SS * KK];   // exp2(c * (right + bias))

// ===========================================================================
// Stage 1: EL = exp2(c*(X@U)) ; ER = exp2(c*(X@W + b_s))
// ===========================================================================
__global__ __launch_bounds__(256) void proj_kernel(
    const float* __restrict__ X,
    const float* __restrict__ U,
    const float* __restrict__ W,
    const float* __restrict__ bs)
{
    const int z  = blockIdx.z;
    const float* Bm = z ? W : U;
    float* out      = z ? g_ER : g_EL;

    __shared__ float As[64][17];
    __shared__ float Bs[16][64];

    const int tx  = threadIdx.x;
    const int ty  = threadIdx.y;
    const int tid = ty * 16 + tx;
    const int m0  = blockIdx.y * 64;
    const int n0  = blockIdx.x * 64;

    float acc[4][4];
#pragma unroll
    for (int u = 0; u < 4; u++)
#pragma unroll
        for (int v = 0; v < 4; v++) acc[u][v] = 0.0f;

    for (int k0 = 0; k0 < HH; k0 += 16) {
#pragma unroll
        for (int l = 0; l < 4; l++) {
            int idx = tid + l * 256;
            int r = idx >> 4, c = idx & 15;
            As[r][c] = X[(size_t)(m0 + r) * HH + k0 + c];
        }
#pragma unroll
        for (int l = 0; l < 4; l++) {
            int idx = tid + l * 256;
            int r = idx >> 6, c = idx & 63;
            Bs[r][c] = Bm[(size_t)(k0 + r) * KK + n0 + c];
        }
        __syncthreads();

#pragma unroll
        for (int kk = 0; kk < 16; kk++) {
            float a[4], b[4];
#pragma unroll
            for (int u = 0; u < 4; u++) a[u] = As[ty * 4 + u][kk];
#pragma unroll
            for (int v = 0; v < 4; v++) b[v] = Bs[kk][tx * 4 + v];
#pragma unroll
            for (int u = 0; u < 4; u++)
#pragma unroll
                for (int v = 0; v < 4; v++)
                    acc[u][v] = fmaf(a[u], b[v], acc[u][v]);
        }
        __syncthreads();
    }

#pragma unroll
    for (int u = 0; u < 4; u++) {
        int row = m0 + ty * 4 + u;
#pragma unroll
        for (int v = 0; v < 4; v++) {
            int col = n0 + tx * 4 + v;
            float val = acc[u][v];
            if (z) val += bs[col];
            val *= TANH_PRESCALE;
            float e;
            asm("ex2.approx.f32 %0, %1;" : "=f"(e) : "f"(val));
            out[(size_t)row * KK + col] = e;
        }
    }
}

// ===========================================================================
// Stage 2: warp-level tf32 mma.sync fused kernel.
// CTA = (b, jblock of 128 j-rows, ichunk of 16 i-values), 256 threads, 8 warps.
// Warp w owns j-rows [jblock*128 + w*16, +16).  N = 56 cols (covers P=50).
// A (tanh values) computed straight into mma fragment registers -- no smem.
// ===========================================================================

#define ER_STRIDE 260                       // bank = (4g + t) pattern: conflict-free
#define SV_FLOATS (32 * 32 * 20)            // 32 kchunks x 32 lanes x 20 (16 used)
#define SMEM2_FLOATS (SV_FLOATS + 128 * ER_STRIDE)
#define SMEM2_BYTES (SMEM2_FLOATS * 4)      // 215040 B

__device__ __forceinline__ uint32_t tanh_tf32(float el, float er) {
    float d = fmaf(el, er, 1.0f);           // exp(2x) + 1
    float rc;
    asm("rcp.approx.f32 %0, %1;" : "=f"(rc) : "f"(d));
    float tv = fmaf(-2.0f, rc, 1.0f);       // tanh(x)
    uint32_t u;
    asm("cvt.rna.tf32.f32 %0, %1;" : "=r"(u) : "f"(tv));
    return u;
}

#define MMA_TF32(C, A0, A1, A2, A3, BX, BY)                                   \
    asm volatile(                                                             \
        "mma.sync.aligned.m16n8k8.row.col.f32.tf32.tf32.f32 "                 \
        "{%0,%1,%2,%3}, {%4,%5,%6,%7}, {%8,%9}, {%0,%1,%2,%3};"               \
        : "+f"(C[0]), "+f"(C[1]), "+f"(C[2]), "+f"(C[3])                      \
        : "r"(A0), "r"(A1), "r"(A2), "r"(A3),                                 \
          "r"(__float_as_uint(BX)), "r"(__float_as_uint(BY)))

__global__ __launch_bounds__(256) void fused_mma_kernel(
    const float* __restrict__ v,
    float* __restrict__ out)
{
    extern __shared__ float sm[];
    float* s_v  = sm;                 // v in fragment order (tf32-rounded)
    float* s_er = sm + SV_FLOATS;     // ER tile, 128 x 256, stride 260

    const int tid  = threadIdx.x;
    const int wid  = tid >> 5;
    const int lane = tid & 31;
    const int g    = lane >> 2;       // groupID
    const int t    = lane & 3;        // threadID_in_group

    const int b      = blockIdx.z;
    const int jblock = blockIdx.y;
    const int ichunk = blockIdx.x;

    // ---- pack v into per-lane fragment order (B frag: b0=(t,g), b1=(t+4,g)) ----
    for (int idx = tid; idx < 32 * 32 * 16; idx += 256) {
        int kc = idx >> 9;
        int L  = (idx >> 4) & 31;
        int q  = idx & 15;
        int k  = kc * 8 + (L & 3) + (q & 1) * 4;
        int n  = (q >> 1) * 8 + (L >> 2);
        float val = (n < PP) ? v[k * PP + n] : 0.0f;
        uint32_t u;
        asm("cvt.rna.tf32.f32 %0, %1;" : "=r"(u) : "f"(val));
        s_v[(kc * 32 + L) * 20 + q] = __uint_as_float(u);
    }

    // ---- load ER tile: 128 j-rows x 256 k ----
    const float* erg = g_ER + ((size_t)(b * SS + jblock * 128)) * KK;
    for (int idx = tid; idx < 128 * 64; idx += 256) {
        int r  = idx >> 6;
        int c4 = idx & 63;
        float4 val = *(const float4*)(erg + (size_t)r * KK + c4 * 4);
        *(float4*)(s_er + r * ER_STRIDE + c4 * 4) = val;
    }
    __syncthreads();

    const float* er_r0 = s_er + (wid * 16 + g) * ER_STRIDE;
    const float* er_r1 = er_r0 + 8 * ER_STRIDE;
    const float* EL_b  = g_EL + ((size_t)(b * SS)) * KK;

    for (int ii = 0; ii < 16; ii++) {
        const int i = ichunk * 16 + ii;
        const float* EL = EL_b + (size_t)i * KK;

        float acc[7][4];
#pragma unroll
        for (int nt = 0; nt < 7; nt++)
#pragma unroll
            for (int q = 0; q < 4; q++) acc[nt][q] = 0.0f;

#pragma unroll 4
        for (int kc = 0; kc < 32; kc++) {
            const float* sp = s_v + (kc * 32 + lane) * 20;
            float4 B0 = *(const float4*)(sp);
            float4 B1 = *(const float4*)(sp + 4);
            float4 B2 = *(const float4*)(sp + 8);
            float4 B3 = *(const float4*)(sp + 12);

            const int k0 = kc * 8;
            float el0 = __ldg(EL + k0 + t);
            float el1 = __ldg(EL + k0 + t + 4);
            float er00 = er_r0[k0 + t];
            float er01 = er_r0[k0 + t + 4];
            float er10 = er_r1[k0 + t];
            float er11 = er_r1[k0 + t + 4];

            // A fragment: a0=(g,t) a1=(g+8,t) a2=(g,t+4) a3=(g+8,t+4)
            uint32_t a0 = tanh_tf32(el0, er00);
            uint32_t a1 = tanh_tf32(el0, er10);
            uint32_t a2 = tanh_tf32(el1, er01);
            uint32_t a3 = tanh_tf32(el1, er11);

            MMA_TF32(acc[0], a0, a1, a2, a3, B0.x, B0.y);
            MMA_TF32(acc[1], a0, a1, a2, a3, B0.z, B0.w);
            MMA_TF32(acc[2], a0, a1, a2, a3, B1.x, B1.y);
            MMA_TF32(acc[3], a0, a1, a2, a3, B1.z, B1.w);
            MMA_TF32(acc[4], a0, a1, a2, a3, B2.x, B2.y);
            MMA_TF32(acc[5], a0, a1, a2, a3, B2.z, B2.w);
            MMA_TF32(acc[6], a0, a1, a2, a3, B3.x, B3.y);
        }

        // ---- epilogue: C frag c0=(g,2t) c1=(g,2t+1) c2=(g+8,2t) c3=(g+8,2t+1)
        const size_t j0 = (size_t)(jblock * 128 + wid * 16 + g);
        float* o0 = out + ((size_t)(b * SS + i) * SS + j0) * PP;
        float* o1 = o0 + (size_t)8 * PP;
#pragma unroll
        for (int nt = 0; nt < 6; nt++) {
            const int col = nt * 8 + 2 * t;
            *(float2*)(o0 + col) = make_float2(acc[nt][0], acc[nt][1]);
            *(float2*)(o1 + col) = make_float2(acc[nt][2], acc[nt][3]);
        }
        if (t == 0) {   // ntile 6: only cols 48,49 are < P
            *(float2*)(o0 + 48) = make_float2(acc[6][0], acc[6][1]);
            *(float2*)(o1 + 48) = make_float2(acc[6][2], acc[6][3]);
        }
    }
}

// ===========================================================================
extern "C" void kernel_launch(void* const* d_in, const int* in_sizes, int n_in,
                              void* d_out, int out_size)
{
    (void)in_sizes; (void)n_in; (void)out_size;
    const float* x   = (const float*)d_in[0];
    const float* u_a = (const float*)d_in[1];
    const float* w_a = (const float*)d_in[2];
    const float* b_s = (const float*)d_in[3];
    const float* v   = (const float*)d_in[4];
    float* out       = (float*)d_out;

    {
        dim3 grid(KK / 64, (BB * SS) / 64, 2);
        dim3 block(16, 16);
        proj_kernel<<<grid, block>>>(x, u_a, w_a, b_s);
    }
    {
        cudaFuncSetAttribute(fused_mma_kernel,
                             cudaFuncAttributeMaxDynamicSharedMemorySize,
                             SMEM2_BYTES);
        dim3 grid(16, 2, BB);      // (ichunk, jblock, b) = 256 CTAs
        fused_mma_kernel<<<grid, 256, SMEM2_BYTES>>>(v, out);
    }
}

// round 6
// speedup vs baseline: 3.0187x; 1.4498x over previous
#include <cuda_runtime.h>
#include <cuda_bf16.h>
#include <cstdint>

// Shapes (fixed)
#define BB   8
#define SS   256
#define HH   768
#define KK   256
#define PP   50

// 2*log2(e): tanh(x) = 1 - 2/(exp2(c*a)*exp2(c*b) + 1),  a+b = x
#define TANH_PRESCALE 2.8853900817779268f

// Device scratch (no allocation allowed in kernel_launch)
__device__ float g_EL[BB * SS * KK];   // exp2(c * left)
__device__ float g_ER[BB * SS * KK];   // exp2(c * (right + bias))

// ===========================================================================
// Stage 1: EL = exp2(c*(X@U)) ; ER = exp2(c*(X@W + b_s))
// ===========================================================================
__global__ __launch_bounds__(256) void proj_kernel(
    const float* __restrict__ X,
    const float* __restrict__ U,
    const float* __restrict__ W,
    const float* __restrict__ bs)
{
    const int z  = blockIdx.z;
    const float* Bm = z ? W : U;
    float* out      = z ? g_ER : g_EL;

    __shared__ float As[64][17];
    __shared__ float Bs[16][64];

    const int tx  = threadIdx.x;
    const int ty  = threadIdx.y;
    const int tid = ty * 16 + tx;
    const int m0  = blockIdx.y * 64;
    const int n0  = blockIdx.x * 64;

    float acc[4][4];
#pragma unroll
    for (int u = 0; u < 4; u++)
#pragma unroll
        for (int v = 0; v < 4; v++) acc[u][v] = 0.0f;

    for (int k0 = 0; k0 < HH; k0 += 16) {
#pragma unroll
        for (int l = 0; l < 4; l++) {
            int idx = tid + l * 256;
            int r = idx >> 4, c = idx & 15;
            As[r][c] = X[(size_t)(m0 + r) * HH + k0 + c];
        }
#pragma unroll
        for (int l = 0; l < 4; l++) {
            int idx = tid + l * 256;
            int r = idx >> 6, c = idx & 63;
            Bs[r][c] = Bm[(size_t)(k0 + r) * KK + n0 + c];
        }
        __syncthreads();

#pragma unroll
        for (int kk = 0; kk < 16; kk++) {
            float a[4], b[4];
#pragma unroll
            for (int u = 0; u < 4; u++) a[u] = As[ty * 4 + u][kk];
#pragma unroll
            for (int v = 0; v < 4; v++) b[v] = Bs[kk][tx * 4 + v];
#pragma unroll
            for (int u = 0; u < 4; u++)
#pragma unroll
                for (int v = 0; v < 4; v++)
                    acc[u][v] = fmaf(a[u], b[v], acc[u][v]);
        }
        __syncthreads();
    }

#pragma unroll
    for (int u = 0; u < 4; u++) {
        int row = m0 + ty * 4 + u;
#pragma unroll
        for (int v = 0; v < 4; v++) {
            int col = n0 + tx * 4 + v;
            float val = acc[u][v];
            if (z) val += bs[col];
            val *= TANH_PRESCALE;
            float e;
            asm("ex2.approx.f32 %0, %1;" : "=f"(e) : "f"(val));
            out[(size_t)row * KK + col] = e;
        }
    }
}

// ===========================================================================
// Stage 2: warp-level tf32 mma.sync fused kernel.
// CTA = (b, jblock of 128 j-rows, ichunk of 16 i-values), 512 threads, 16 warps.
// Warp w: j-rows [jblock*128 + (w&7)*16, +16); handles ii = 2*step + (w>>3).
// N = 56 cols (covers P=50). A (tanh) computed straight into fragment regs.
// ===========================================================================

#define ER_STRIDE 260                       // bank = (4g + t) pattern: conflict-free
#define SV_FLOATS (32 * 32 * 20)            // 32 kchunks x 32 lanes x 20 (16 used)
#define SMEM2_FLOATS (SV_FLOATS + 128 * ER_STRIDE)
#define SMEM2_BYTES (SMEM2_FLOATS * 4)      // 215040 B

__device__ __forceinline__ uint32_t tanh_tf32(float el, float er) {
    float d = fmaf(el, er, 1.0f);           // exp(2x) + 1
    float rc;
    asm("rcp.approx.f32 %0, %1;" : "=f"(rc) : "f"(d));
    float tv = fmaf(-2.0f, rc, 1.0f);       // tanh(x)
    uint32_t u;
    asm("cvt.rna.tf32.f32 %0, %1;" : "=r"(u) : "f"(tv));
    return u;
}

#define MMA_TF32(C, A0, A1, A2, A3, BX, BY)                                   \
    asm volatile(                                                             \
        "mma.sync.aligned.m16n8k8.row.col.f32.tf32.tf32.f32 "                 \
        "{%0,%1,%2,%3}, {%4,%5,%6,%7}, {%8,%9}, {%0,%1,%2,%3};"               \
        : "+f"(C[0]), "+f"(C[1]), "+f"(C[2]), "+f"(C[3])                      \
        : "r"(A0), "r"(A1), "r"(A2), "r"(A3),                                 \
          "r"(__float_as_uint(BX)), "r"(__float_as_uint(BY)))

__global__ __launch_bounds__(512, 1) void fused_mma_kernel(
    const float* __restrict__ v,
    float* __restrict__ out)
{
    extern __shared__ float sm[];
    float* s_v  = sm;                 // v in fragment order (tf32-rounded)
    float* s_er = sm + SV_FLOATS;     // ER tile, 128 x 256, stride 260

    const int tid  = threadIdx.x;
    const int wid  = tid >> 5;        // 0..15
    const int lane = tid & 31;
    const int g    = lane >> 2;       // groupID
    const int t    = lane & 3;        // threadID_in_group
    const int jw   = wid & 7;         // j-subtile (16 rows each)
    const int ih   = wid >> 3;        // ii parity (0 or 1)

    const int b      = blockIdx.z;
    const int jblock = blockIdx.y;
    const int ichunk = blockIdx.x;

    // ---- pack v into per-lane fragment order (B frag: b0=(t,g), b1=(t+4,g)) ----
    for (int idx = tid; idx < 32 * 32 * 16; idx += 512) {
        int kc = idx >> 9;
        int L  = (idx >> 4) & 31;
        int q  = idx & 15;
        int k  = kc * 8 + (L & 3) + (q & 1) * 4;
        int n  = (q >> 1) * 8 + (L >> 2);
        float val = (n < PP) ? v[k * PP + n] : 0.0f;
        uint32_t u;
        asm("cvt.rna.tf32.f32 %0, %1;" : "=r"(u) : "f"(val));
        s_v[(kc * 32 + L) * 20 + q] = __uint_as_float(u);
    }

    // ---- load ER tile: 128 j-rows x 256 k ----
    const float* erg = g_ER + ((size_t)(b * SS + jblock * 128)) * KK;
    for (int idx = tid; idx < 128 * 64; idx += 512) {
        int r  = idx >> 6;
        int c4 = idx & 63;
        float4 val = *(const float4*)(erg + (size_t)r * KK + c4 * 4);
        *(float4*)(s_er + r * ER_STRIDE + c4 * 4) = val;
    }
    __syncthreads();

    const float* er_r0 = s_er + (jw * 16 + g) * ER_STRIDE;
    const float* er_r1 = er_r0 + 8 * ER_STRIDE;
    const float* EL_b  = g_EL + ((size_t)(b * SS)) * KK;

    for (int step = 0; step < 8; step++) {
        const int ii = step * 2 + ih;
        const int i  = ichunk * 16 + ii;
        const float* EL = EL_b + (size_t)i * KK;

        float acc[7][4];
#pragma unroll
        for (int nt = 0; nt < 7; nt++)
#pragma unroll
            for (int q = 0; q < 4; q++) acc[nt][q] = 0.0f;

#pragma unroll 4
        for (int kc = 0; kc < 32; kc++) {
            const float* sp = s_v + (kc * 32 + lane) * 20;
            float4 B0 = *(const float4*)(sp);
            float4 B1 = *(const float4*)(sp + 4);
            float4 B2 = *(const float4*)(sp + 8);
            float4 B3 = *(const float4*)(sp + 12);

            const int k0 = kc * 8;
            float el0 = __ldg(EL + k0 + t);
            float el1 = __ldg(EL + k0 + t + 4);
            float er00 = er_r0[k0 + t];
            float er01 = er_r0[k0 + t + 4];
            float er10 = er_r1[k0 + t];
            float er11 = er_r1[k0 + t + 4];

            // A fragment: a0=(g,t) a1=(g+8,t) a2=(g,t+4) a3=(g+8,t+4)
            uint32_t a0 = tanh_tf32(el0, er00);
            uint32_t a1 = tanh_tf32(el0, er10);
            uint32_t a2 = tanh_tf32(el1, er01);
            uint32_t a3 = tanh_tf32(el1, er11);

            MMA_TF32(acc[0], a0, a1, a2, a3, B0.x, B0.y);
            MMA_TF32(acc[1], a0, a1, a2, a3, B0.z, B0.w);
            MMA_TF32(acc[2], a0, a1, a2, a3, B1.x, B1.y);
            MMA_TF32(acc[3], a0, a1, a2, a3, B1.z, B1.w);
            MMA_TF32(acc[4], a0, a1, a2, a3, B2.x, B2.y);
            MMA_TF32(acc[5], a0, a1, a2, a3, B2.z, B2.w);
            MMA_TF32(acc[6], a0, a1, a2, a3, B3.x, B3.y);
        }

        // ---- epilogue: C frag c0=(g,2t) c1=(g,2t+1) c2=(g+8,2t) c3=(g+8,2t+1)
        const size_t j0 = (size_t)(jblock * 128 + jw * 16 + g);
        float* o0 = out + ((size_t)(b * SS + i) * SS + j0) * PP;
        float* o1 = o0 + (size_t)8 * PP;
#pragma unroll
        for (int nt = 0; nt < 6; nt++) {
            const int col = nt * 8 + 2 * t;
            *(float2*)(o0 + col) = make_float2(acc[nt][0], acc[nt][1]);
            *(float2*)(o1 + col) = make_float2(acc[nt][2], acc[nt][3]);
        }
        if (t == 0) {   // ntile 6: only cols 48,49 are < P
            *(float2*)(o0 + 48) = make_float2(acc[6][0], acc[6][1]);
            *(float2*)(o1 + 48) = make_float2(acc[6][2], acc[6][3]);
        }
    }
}

// ===========================================================================
extern "C" void kernel_launch(void* const* d_in, const int* in_sizes, int n_in,
                              void* d_out, int out_size)
{
    (void)in_sizes; (void)n_in; (void)out_size;
    const float* x   = (const float*)d_in[0];
    const float* u_a = (const float*)d_in[1];
    const float* w_a = (const float*)d_in[2];
    const float* b_s = (const float*)d_in[3];
    const float* v   = (const float*)d_in[4];
    float* out       = (float*)d_out;

    {
        dim3 grid(KK / 64, (BB * SS) / 64, 2);
        dim3 block(16, 16);
        proj_kernel<<<grid, block>>>(x, u_a, w_a, b_s);
    }
    {
        cudaFuncSetAttribute(fused_mma_kernel,
                             cudaFuncAttributeMaxDynamicSharedMemorySize,
                             SMEM2_BYTES);
        dim3 grid(16, 2, BB);      // (ichunk, jblock, b) = 256 CTAs
        fused_mma_kernel<<<grid, 512, SMEM2_BYTES>>>(v, out);
    }
}